// round 15
// baseline (speedup 1.0000x reference)
#include <cuda_runtime.h>
#include <cuda_fp16.h>
#include <cstdint>

#define BB 4
#define CC 192
#define NN 4096
#define KK 9
#define NCAND 16
#define NLIST 17

__device__ __align__(256) float  g_xn[(size_t)BB * CC * NN];   // normalized [b][c][n]
__device__ __align__(256) float  g_xnt[(size_t)BB * NN * CC];  // transposed [b][n][c]
__device__ __align__(256) float  g_sq[(size_t)BB * NN];
__device__ __align__(256) __half g_xh[(size_t)BB * CC * NN];   // fp16 [b][c][n]
__device__ __align__(256) int    g_cand[(size_t)BB * NN * NCAND];

__device__ __forceinline__ uint32_t smem_u32(const void* p) {
    uint32_t a;
    asm("{ .reg .u64 t; cvta.to.shared.u64 t, %1; cvt.u32.u64 %0, t; }" : "=r"(a) : "l"(p));
    return a;
}
__device__ __forceinline__ void cp_async16(uint32_t smem_dst, const void* gmem_src) {
    asm volatile("cp.async.ca.shared.global [%0], [%1], 16;\n" :: "r"(smem_dst), "l"(gmem_src));
}
__device__ __forceinline__ void cp_commit() { asm volatile("cp.async.commit_group;\n"); }
template <int N>
__device__ __forceinline__ void cp_wait() { asm volatile("cp.async.wait_group %0;\n" :: "n"(N)); }

__device__ __forceinline__ void ldsm_x4_t(uint32_t* r, uint32_t addr) {
    asm volatile("ldmatrix.sync.aligned.m8n8.x4.trans.shared.b16 {%0,%1,%2,%3}, [%4];"
                 : "=r"(r[0]), "=r"(r[1]), "=r"(r[2]), "=r"(r[3]) : "r"(addr));
}
__device__ __forceinline__ void mma_f16(float* c, const uint32_t* a, const uint32_t* b) {
    asm volatile(
        "mma.sync.aligned.m16n8k16.row.col.f32.f16.f16.f32 "
        "{%0,%1,%2,%3}, {%4,%5,%6,%7}, {%8,%9}, {%0,%1,%2,%3};"
        : "+f"(c[0]), "+f"(c[1]), "+f"(c[2]), "+f"(c[3])
        : "r"(a[0]), "r"(a[1]), "r"(a[2]), "r"(a[3]), "r"(b[0]), "r"(b[1]));
}
__device__ __forceinline__ unsigned ford(float f) {
    unsigned u = __float_as_uint(f);
    return (u & 0x80000000u) ? ~u : (u | 0x80000000u);
}

// ---------------------------------------------------------------------------
// Kernel 1: normalize; writes fp32 [c][n], fp16 [c][n], sq.
// ---------------------------------------------------------------------------
__global__ void normalize_kernel(const float* __restrict__ x) {
    int b = blockIdx.y;
    int n = blockIdx.x * blockDim.x + threadIdx.x;
    if (n >= NN) return;
    const float* xb = x + (size_t)b * CC * NN + n;
    float s = 0.f;
    #pragma unroll 16
    for (int c = 0; c < CC; c++) { float v = xb[(size_t)c * NN]; s += v * v; }
    float denom = fmaxf(sqrtf(s), 1e-12f);
    float* xnb = g_xn + (size_t)b * CC * NN + n;
    __half* xhb = g_xh + (size_t)b * CC * NN + n;
    float sq = 0.f;
    #pragma unroll 16
    for (int c = 0; c < CC; c++) {
        float p = xb[(size_t)c * NN] / denom;
        xnb[(size_t)c * NN] = p;
        xhb[(size_t)c * NN] = __float2half(p);
        sq += p * p;
    }
    g_sq[(size_t)b * NN + n] = sq;
}

// ---------------------------------------------------------------------------
// Kernel 2: 32x32 tiled transpose g_xn [c][n] -> g_xnt [n][c].
// ---------------------------------------------------------------------------
__global__ void transpose_kernel() {
    __shared__ float t[32][33];
    int b = blockIdx.z, c0 = blockIdx.x * 32, n0 = blockIdx.y * 32;
    int tx = threadIdx.x, ty = threadIdx.y;
    const float* src = g_xn + (size_t)b * CC * NN;
    float* dst = g_xnt + (size_t)b * NN * CC;
    #pragma unroll
    for (int i = 0; i < 4; i++)
        t[ty + 8 * i][tx] = src[(size_t)(c0 + ty + 8 * i) * NN + n0 + tx];
    __syncthreads();
    #pragma unroll
    for (int i = 0; i < 4; i++)
        dst[(size_t)(n0 + ty + 8 * i) * CC + c0 + tx] = t[tx][ty + 8 * i];
}

// ---------------------------------------------------------------------------
// Kernel 3: fused fp16-mma distance + top-17 selection.
// Block = 128 n-rows x full m sweep (128 chunks of 32). 256 thr, 8 warps.
// smem: A [k=192][n=128+pad8] fp16, B 2x [k=192][m=32+pad8] fp16, D 128x33 f32.
// ---------------------------------------------------------------------------
#define AS_STRIDE 136
#define BS_STRIDE 40
#define A_BYTES (CC * AS_STRIDE * 2)          // 52224
#define B_BYTES (CC * BS_STRIDE * 2)          // 15360
#define SM_A  0
#define SM_B0 A_BYTES
#define SM_B1 (A_BYTES + B_BYTES)
#define SM_D  (A_BYTES + 2 * B_BYTES)         // 82944
#define SM_TOTAL (SM_D + 128 * 33 * 4)        // 99840

__global__ __launch_bounds__(256) void knn_mma_kernel() {
    extern __shared__ unsigned char smraw[];
    const uint32_t sb = smem_u32(smraw);
    const int tid = threadIdx.x;
    const int lane = tid & 31;
    const int w = tid >> 5;
    const int b = blockIdx.y;
    const int n0 = blockIdx.x * 128;
    const __half* xh = g_xh + (size_t)b * CC * NN;
    const float* sqb = g_sq + (size_t)b * NN;

    // ---- issue A load (group 1): 192 rows x 128 halves ----
    {
        const int seg = tid & 15;             // 16B segment within row
        #pragma unroll
        for (int i = 0; i < 12; i++) {
            int row = (tid >> 4) + 16 * i;    // k-row (channel)
            cp_async16(sb + SM_A + row * AS_STRIDE * 2 + seg * 16,
                       (const char*)(xh + (size_t)row * NN + n0) + seg * 16);
        }
        cp_commit();
    }
    // ---- issue B chunk 0 (group 2) ----
    {
        const int seg = tid & 3;
        #pragma unroll
        for (int i = 0; i < 3; i++) {
            int row = (tid >> 2) + 64 * i;
            cp_async16(sb + SM_B0 + row * BS_STRIDE * 2 + seg * 16,
                       (const char*)(xh + (size_t)row * NN) + seg * 16);
        }
        cp_commit();
    }

    cp_wait<1>();            // A complete
    __syncthreads();

    // ---- load A fragments once (12 k-chunks x 4 regs) ----
    uint32_t af[12][4];
    {
        const int q = lane >> 3, tr = lane & 7;
        const int arow = tr + ((q >= 2) ? 8 : 0);
        const int acol = w * 16 + (((q & 1) == 1) ? 8 : 0);
        #pragma unroll
        for (int kc = 0; kc < 12; kc++) {
            uint32_t addr = sb + SM_A + ((16 * kc + arow) * AS_STRIDE + acol) * 2;
            ldsm_x4_t(af[kc], addr);
        }
    }

    // selection state: 2 threads per row
    const int srow = tid >> 1;        // 0..127
    const int shalf = tid & 1;
    const int gn = n0 + srow;
    const float sqn = sqb[gn];
    float v[NLIST]; int id[NLIST];
    #pragma unroll
    for (int k = 0; k < NLIST; k++) { v[k] = 3.4e38f; id[k] = 0x7FFFFFFF; }
    float vmax = 3.4e38f; int idmax = 0x7FFFFFFF;

    const int bq = lane >> 3, btr = lane & 7;
    const int brow = btr + (((bq & 1) == 1) ? 8 : 0);
    const int bcoff = (bq >= 2) ? 8 : 0;
    float* D = (float*)(smraw + SM_D);

    float acc[4][4];
    #pragma unroll
    for (int ct = 0; ct < 4; ct++)
        #pragma unroll
        for (int q = 0; q < 4; q++) acc[ct][q] = 0.f;

    #pragma unroll 1
    for (int t = 0; t < 128; t++) {
        const uint32_t bcur = (t & 1) ? SM_B1 : SM_B0;
        if (t + 1 < 128) {
            const uint32_t bnxt = (t & 1) ? SM_B0 : SM_B1;
            const int seg = tid & 3;
            #pragma unroll
            for (int i = 0; i < 3; i++) {
                int row = (tid >> 2) + 64 * i;
                cp_async16(sb + bnxt + row * BS_STRIDE * 2 + seg * 16,
                           (const char*)(xh + (size_t)row * NN + (t + 1) * 32) + seg * 16);
            }
            cp_commit();
            cp_wait<1>();
        } else {
            cp_wait<0>();
        }
        __syncthreads();

        // mma over 12 k-chunks, 4 coltiles (2 ldmatrix.x4 pairs)
        #pragma unroll
        for (int kc = 0; kc < 12; kc++) {
            #pragma unroll
            for (int p = 0; p < 2; p++) {
                uint32_t bf[4];
                uint32_t addr = sb + bcur +
                    ((16 * kc + brow) * BS_STRIDE + p * 16 + bcoff) * 2;
                ldsm_x4_t(bf, addr);
                mma_f16(acc[2 * p],     af[kc], bf);
                mma_f16(acc[2 * p + 1], af[kc], bf + 2);
            }
        }

        // stage D tile (128 x 32)
        {
            const int r1 = w * 16 + (lane >> 2);
            const int cb = 2 * (lane & 3);
            #pragma unroll
            for (int ct = 0; ct < 4; ct++) {
                int c = ct * 8 + cb;
                D[r1 * 33 + c]           = acc[ct][0];
                D[r1 * 33 + c + 1]       = acc[ct][1];
                D[(r1 + 8) * 33 + c]     = acc[ct][2];
                D[(r1 + 8) * 33 + c + 1] = acc[ct][3];
                acc[ct][0] = acc[ct][1] = acc[ct][2] = acc[ct][3] = 0.f;
            }
        }
        __syncthreads();

        // select 16 values for (srow, shalf)
        {
            const int mb = t * 32 + shalf * 16;
            const float* drow = &D[srow * 33 + shalf * 16];
            #pragma unroll 4
            for (int j = 0; j < 16; j++) {
                int m = mb + j;
                float d = (sqn + (-2.0f * drow[j])) + sqb[m];
                if ((d < vmax) || (d == vmax && m < idmax)) {
                    v[NLIST - 1] = d; id[NLIST - 1] = m;
                    #pragma unroll
                    for (int k = NLIST - 1; k > 0; k--) {
                        bool sw = (v[k] < v[k-1]) || (v[k] == v[k-1] && id[k] < id[k-1]);
                        if (sw) {
                            float tv = v[k]; v[k] = v[k-1]; v[k-1] = tv;
                            int ti = id[k]; id[k] = id[k-1]; id[k-1] = ti;
                        }
                    }
                    vmax = v[NLIST - 1]; idmax = id[NLIST - 1];
                }
            }
        }
        __syncthreads();
    }

    // ---- merge half-lists (even lane takes odd partner's) -> candidates ----
    float pv[NLIST]; int pid[NLIST];
    #pragma unroll
    for (int k = 0; k < NLIST; k++) {
        pv[k]  = __shfl_down_sync(0xFFFFFFFFu, v[k], 1);
        pid[k] = __shfl_down_sync(0xFFFFFFFFu, id[k], 1);
    }
    if ((tid & 1) == 0) {
        int ia = 0, ib = 0, wc = 0;
        int* dst = g_cand + ((size_t)b * NN + gn) * NCAND;
        #pragma unroll 1
        for (int r = 0; r < NLIST && wc < NCAND; r++) {
            bool takeA;
            if (ia >= NLIST) takeA = false;
            else if (ib >= NLIST) takeA = true;
            else takeA = (v[ia] < pv[ib]) || (v[ia] == pv[ib] && id[ia] < pid[ib]);
            int sel = takeA ? id[ia] : pid[ib];
            if (takeA) ia++; else ib++;
            if (sel != gn) dst[wc++] = sel;
        }
    }
}

// ---------------------------------------------------------------------------
// Kernel 4: exact fp32 rescore (c-ascending fmaf chain, bit-identical to
// the verified round-8 numerics), reads transposed g_xnt for coalescing.
// ---------------------------------------------------------------------------
__global__ void rescore_kernel(float* __restrict__ out) {
    const int warp = (blockIdx.x * blockDim.x + threadIdx.x) >> 5;
    const int lane = threadIdx.x & 31;
    if (warp >= BB * NN) return;
    const int row = warp;
    const int b = row >> 12;
    const int n = row & (NN - 1);
    const float* vn = g_xnt + ((size_t)b * NN + n) * CC;
    const float* sqb = g_sq + (size_t)b * NN;

    unsigned long long key = 0xFFFFFFFFFFFFFFFFULL;
    if (lane < NCAND) {
        int m = g_cand[(size_t)row * NCAND + lane];
        const float* vm = g_xnt + ((size_t)b * NN + m) * CC;
        float acc = 0.f;
        #pragma unroll 4
        for (int c4 = 0; c4 < CC / 4; c4++) {
            float4 a = *(const float4*)&vn[c4 * 4];
            float4 bb = *(const float4*)&vm[c4 * 4];
            acc = fmaf(a.x, bb.x, acc);
            acc = fmaf(a.y, bb.y, acc);
            acc = fmaf(a.z, bb.z, acc);
            acc = fmaf(a.w, bb.w, acc);
        }
        float d = (sqb[n] + (-2.0f * acc)) + sqb[m];
        key = ((unsigned long long)ford(d) << 32) | (unsigned)m;
    }

    const size_t L = (size_t)BB * NN * KK;
    const size_t outbase = (size_t)row * KK;
    for (int k = 0; k < KK; k++) {
        unsigned long long mn = key;
        #pragma unroll
        for (int off = 16; off > 0; off >>= 1) {
            unsigned long long o = __shfl_xor_sync(0xFFFFFFFFu, mn, off);
            mn = (o < mn) ? o : mn;
        }
        if (key == mn) key = 0xFFFFFFFFFFFFFFFFULL;
        if (lane == 0)
            out[outbase + k] = (float)((int)(mn & 0xFFFFFFFFu) + b * NN);
    }
    if (lane < KK) out[L + outbase + lane] = (float)(n + b * NN);
}

// ---------------------------------------------------------------------------
extern "C" void kernel_launch(void* const* d_in, const int* in_sizes, int n_in,
                              void* d_out, int out_size) {
    const float* x = (const float*)d_in[0];
    float* out = (float*)d_out;

    cudaFuncSetAttribute(knn_mma_kernel,
                         cudaFuncAttributeMaxDynamicSharedMemorySize, SM_TOTAL);

    { dim3 grid(NN / 256, BB); normalize_kernel<<<grid, 256>>>(x); }
    { dim3 grid(CC / 32, NN / 32, BB); transpose_kernel<<<grid, dim3(32, 8)>>>(); }
    { dim3 grid(NN / 128, BB); knn_mma_kernel<<<grid, 256, SM_TOTAL>>>(); }
    { int rows = BB * NN; rescore_kernel<<<(rows * 32 + 255) / 256, 256>>>(out); }
}

// round 16
// speedup vs baseline: 2.1374x; 2.1374x over previous
#include <cuda_runtime.h>
#include <cuda_fp16.h>
#include <cstdint>

#define BB 4
#define CC 192
#define NN 4096
#define KK 9
#define NCAND 16
#define TKH 16

__device__ __align__(256) float    g_xn[(size_t)BB * CC * NN];      // normalized [b][c][n]
__device__ __align__(256) float    g_xnt[(size_t)BB * NN * CC];     // transposed [b][n][c]
__device__ __align__(256) float    g_sq[(size_t)BB * NN];
__device__ __align__(256) uint32_t g_xdup[(size_t)BB * CC * NN];    // half2(v,v)
__device__ __align__(256) uint32_t g_xpair[(size_t)BB * CC * (NN/2)]; // half2(v_n, v_n+1)
__device__ __align__(256) float    g_dist[(size_t)BB * NN * NN];
__device__ __align__(256) int      g_cand[(size_t)BB * NN * NCAND];

__device__ __forceinline__ void cp_async16(void* smem_dst, const void* gmem_src) {
    unsigned saddr = (unsigned)__cvta_generic_to_shared(smem_dst);
    asm volatile("cp.async.ca.shared.global [%0], [%1], 16;\n" :: "r"(saddr), "l"(gmem_src));
}
__device__ __forceinline__ void cp_commit() { asm volatile("cp.async.commit_group;\n"); }
template <int N>
__device__ __forceinline__ void cp_wait() { asm volatile("cp.async.wait_group %0;\n" :: "n"(N)); }

__device__ __forceinline__ unsigned ford(float f) {
    unsigned u = __float_as_uint(f);
    return (u & 0x80000000u) ? ~u : (u | 0x80000000u);
}

// ---------------------------------------------------------------------------
// Kernel 1: normalize; thread handles 2 adjacent columns; emits fp32, dup-
// packed half2, pair-packed half2, and sq.
// ---------------------------------------------------------------------------
__global__ void normalize_kernel(const float* __restrict__ x) {
    int b = blockIdx.y;
    int t = blockIdx.x * blockDim.x + threadIdx.x;   // 0..2047
    if (t >= NN / 2) return;
    int n = t * 2;
    const float* xb = x + (size_t)b * CC * NN;

    float s0 = 0.f, s1 = 0.f;
    #pragma unroll 8
    for (int c = 0; c < CC; c++) {
        float2 v = *(const float2*)(xb + (size_t)c * NN + n);
        s0 += v.x * v.x; s1 += v.y * v.y;
    }
    float d0 = fmaxf(sqrtf(s0), 1e-12f);
    float d1 = fmaxf(sqrtf(s1), 1e-12f);

    float* xnb = g_xn + (size_t)b * CC * NN;
    uint32_t* xd = g_xdup + (size_t)b * CC * NN;
    uint32_t* xp = g_xpair + (size_t)b * CC * (NN / 2);
    float sq0 = 0.f, sq1 = 0.f;
    #pragma unroll 8
    for (int c = 0; c < CC; c++) {
        float2 v = *(const float2*)(xb + (size_t)c * NN + n);
        float p0 = v.x / d0, p1 = v.y / d1;
        *(float2*)(xnb + (size_t)c * NN + n) = make_float2(p0, p1);
        unsigned h0 = __half_as_ushort(__float2half(p0));
        unsigned h1 = __half_as_ushort(__float2half(p1));
        uint2 dup = make_uint2((h0 << 16) | h0, (h1 << 16) | h1);
        *(uint2*)(xd + (size_t)c * NN + n) = dup;
        xp[(size_t)c * (NN / 2) + t] = (h1 << 16) | h0;
        sq0 += p0 * p0; sq1 += p1 * p1;
    }
    g_sq[(size_t)b * NN + n] = sq0;
    g_sq[(size_t)b * NN + n + 1] = sq1;
}

// ---------------------------------------------------------------------------
// Kernel 2: 32x32 tiled transpose g_xn [c][n] -> g_xnt [n][c] (for rescore).
// ---------------------------------------------------------------------------
__global__ void transpose_kernel() {
    __shared__ float t[32][33];
    int b = blockIdx.z, c0 = blockIdx.x * 32, n0 = blockIdx.y * 32;
    int tx = threadIdx.x, ty = threadIdx.y;
    const float* src = g_xn + (size_t)b * CC * NN;
    float* dst = g_xnt + (size_t)b * NN * CC;
    #pragma unroll
    for (int i = 0; i < 4; i++)
        t[ty + 8 * i][tx] = src[(size_t)(c0 + ty + 8 * i) * NN + n0 + tx];
    __syncthreads();
    #pragma unroll
    for (int i = 0; i < 4; i++)
        dst[(size_t)(n0 + ty + 8 * i) * CC + c0 + tx] = t[tx][ty + 8 * i];
}

// ---------------------------------------------------------------------------
// Kernel 3: half2 SIMT symmetric distance GEMM. Block tile 128n x 256m,
// 256 threads, 8n x 8half2 (16m) per thread, HFMA2 inner loop,
// cp.async double-buffer (round-12 skeleton). Blocks: {(I,J): I <= 2J+1}.
// Mirror tile written (raw-dot smem transpose) only when I < 2J.
// ---------------------------------------------------------------------------
__global__ __launch_bounds__(256) void dist_gemm_h2_kernel() {
    __shared__ union {
        uint32_t ab[2][2][TKH][128];   // [buf][A=0/B=1][k][u32 col] -> 32 KB
        float ts[128 * 33];            // raw-dot transpose staging
    } sm;

    // block mapping: J = m-block (256 wide), I = n-block (128 tall), I <= 2J+1
    int u = blockIdx.x, J = 0;
    for (;;) { int cnt = 2 * J + 2; if (u < cnt) break; u -= cnt; J++; }
    const int I = u;
    const int b  = blockIdx.y;
    const int n0 = I * 128;
    const int m0 = J * 256;
    const int mp0 = J * 128;                 // pair-index base

    const uint32_t* xd = g_xdup + (size_t)b * CC * NN;
    const uint32_t* xp = g_xpair + (size_t)b * CC * (NN / 2);
    const int tid = threadIdx.x;
    const int tx = tid & 15;                 // m-pair micro-tile
    const int ty = tid >> 4;                 // n micro-tile
    const int lr = tid >> 5;                 // loader k-row 0..7
    const int lane = tid & 31;

    // preload tile 0
    {
        cp_async16(&sm.ab[0][0][lr][lane * 4],     xd + (size_t)lr * NN + n0 + lane * 4);
        cp_async16(&sm.ab[0][0][lr + 8][lane * 4], xd + (size_t)(lr + 8) * NN + n0 + lane * 4);
        cp_async16(&sm.ab[0][1][lr][lane * 4],     xp + (size_t)lr * (NN / 2) + mp0 + lane * 4);
        cp_async16(&sm.ab[0][1][lr + 8][lane * 4], xp + (size_t)(lr + 8) * (NN / 2) + mp0 + lane * 4);
        cp_commit();
    }

    __half2 acc2[8][8];
    #pragma unroll
    for (int i = 0; i < 8; i++)
        #pragma unroll
        for (int j = 0; j < 8; j++) acc2[i][j] = __float2half2_rn(0.f);

    const int NT = CC / TKH;   // 12
    #pragma unroll 1
    for (int t = 0; t < NT; t++) {
        const int cur = t & 1;
        if (t + 1 < NT) {
            const int c1 = (t + 1) * TKH;
            cp_async16(&sm.ab[cur ^ 1][0][lr][lane * 4],     xd + (size_t)(c1 + lr) * NN + n0 + lane * 4);
            cp_async16(&sm.ab[cur ^ 1][0][lr + 8][lane * 4], xd + (size_t)(c1 + lr + 8) * NN + n0 + lane * 4);
            cp_async16(&sm.ab[cur ^ 1][1][lr][lane * 4],     xp + (size_t)(c1 + lr) * (NN / 2) + mp0 + lane * 4);
            cp_async16(&sm.ab[cur ^ 1][1][lr + 8][lane * 4], xp + (size_t)(c1 + lr + 8) * (NN / 2) + mp0 + lane * 4);
            cp_commit();
            cp_wait<1>();
        } else {
            cp_wait<0>();
        }
        __syncthreads();

        #pragma unroll
        for (int kk = 0; kk < TKH; kk++) {
            __half2 a[8], bv[8];
            #pragma unroll
            for (int i = 0; i < 8; i++)
                a[i] = *reinterpret_cast<const __half2*>(&sm.ab[cur][0][kk][ty * 8 + i]);
            #pragma unroll
            for (int j = 0; j < 8; j++)
                bv[j] = *reinterpret_cast<const __half2*>(&sm.ab[cur][1][kk][tx * 8 + j]);
            #pragma unroll
            for (int i = 0; i < 8; i++)
                #pragma unroll
                for (int j = 0; j < 8; j++)
                    acc2[i][j] = __hfma2(a[i], bv[j], acc2[i][j]);
        }
        __syncthreads();
    }

    const float* sqb = g_sq + (size_t)b * NN;

    // ---- normal tile: dist[n][m] = (sq_n + (-2*dot)) + sq_m ----
    {
        float sqm[16];
        #pragma unroll
        for (int j = 0; j < 16; j++) sqm[j] = sqb[m0 + tx * 16 + j];
        #pragma unroll
        for (int i = 0; i < 8; i++) {
            int n = n0 + ty * 8 + i;
            float sqn = sqb[n];
            float o[16];
            #pragma unroll
            for (int j = 0; j < 8; j++) {
                float2 f = __half22float2(acc2[i][j]);
                o[2 * j]     = (sqn + (-2.0f * f.x)) + sqm[2 * j];
                o[2 * j + 1] = (sqn + (-2.0f * f.y)) + sqm[2 * j + 1];
            }
            float* drow = g_dist + ((size_t)b * NN + n) * NN + m0 + tx * 16;
            #pragma unroll
            for (int q = 0; q < 4; q++)
                *(float4*)&drow[q * 4] = make_float4(o[q*4], o[q*4+1], o[q*4+2], o[q*4+3]);
        }
    }

    // ---- mirrored tile: dist[m][n] = (sq_m + (-2*dot)) + sq_n ----
    if (I < 2 * J) {
        #pragma unroll 1
        for (int c8 = 0; c8 < 8; c8++) {         // m'-chunks of 32
            __syncthreads();
            if ((tx >> 1) == c8) {               // tx in {2c8, 2c8+1}
                #pragma unroll
                for (int i = 0; i < 8; i++) {
                    int rl = ty * 8 + i;
                    #pragma unroll
                    for (int j = 0; j < 8; j++) {
                        float2 f = __half22float2(acc2[i][j]);
                        int ml = (tx & 1) * 16 + 2 * j;
                        sm.ts[(size_t)rl * 33 + ml]     = f.x;
                        sm.ts[(size_t)rl * 33 + ml + 1] = f.y;
                    }
                }
            }
            __syncthreads();
            int rl = tid >> 3;                   // 0..31
            int cg = (tid & 7) * 16;             // col group base
            int m = m0 + c8 * 32 + rl;
            float sqm_v = sqb[m];
            float* drow = g_dist + ((size_t)b * NN + m) * NN + n0;
            float o[16];
            #pragma unroll
            for (int cc = 0; cc < 16; cc++) {
                float dot = sm.ts[(size_t)(cg + cc) * 33 + rl];
                o[cc] = (sqm_v + (-2.0f * dot)) + sqb[n0 + cg + cc];
            }
            #pragma unroll
            for (int q = 0; q < 4; q++)
                *(float4*)&drow[cg + q * 4] = make_float4(o[q*4], o[q*4+1], o[q*4+2], o[q*4+3]);
        }
    }
}

// ---------------------------------------------------------------------------
// Kernel 4: warp-per-row top-17 -> 16 non-self candidates (proven, round 13).
// ---------------------------------------------------------------------------
__global__ void select_cand_kernel() {
    const int warp = (blockIdx.x * blockDim.x + threadIdx.x) >> 5;
    const int lane = threadIdx.x & 31;
    if (warp >= BB * NN) return;
    const int row = warp;
    const int n = row & (NN - 1);
    const float* drow = g_dist + (size_t)row * NN;

    float v[17]; int id[17];
    #pragma unroll
    for (int k = 0; k < 17; k++) { v[k] = 3.4e38f; id[k] = 0x7FFFFFFF; }

    for (int m = lane; m < NN; m += 32) {
        float val = drow[m];
        if ((val < v[16]) || (val == v[16] && m < id[16])) {
            v[16] = val; id[16] = m;
            #pragma unroll
            for (int k = 16; k > 0; k--) {
                bool sw = (v[k] < v[k-1]) || (v[k] == v[k-1] && id[k] < id[k-1]);
                if (sw) {
                    float tv = v[k]; v[k] = v[k-1]; v[k-1] = tv;
                    int ti = id[k]; id[k] = id[k-1]; id[k-1] = ti;
                }
            }
        }
    }

    int pos = 0, wcount = 0;
    for (int r = 0; r < 17; r++) {
        unsigned long long myk = (pos < 17)
            ? (((unsigned long long)ford(v[pos]) << 32) | (unsigned)id[pos])
            : 0xFFFFFFFFFFFFFFFFULL;
        unsigned long long mn = myk;
        #pragma unroll
        for (int off = 16; off > 0; off >>= 1) {
            unsigned long long o = __shfl_xor_sync(0xFFFFFFFFu, mn, off);
            mn = (o < mn) ? o : mn;
        }
        if (myk == mn) pos++;
        if (lane == 0) {
            int idv = (int)(mn & 0xFFFFFFFFu);
            if (idv != n && wcount < NCAND)
                g_cand[(size_t)row * NCAND + wcount++] = idv;
        }
    }
}

// ---------------------------------------------------------------------------
// Kernel 5: exact fp32 rescore (c-ascending fmaf, round-8-identical numerics).
// ---------------------------------------------------------------------------
__global__ void rescore_kernel(float* __restrict__ out) {
    const int warp = (blockIdx.x * blockDim.x + threadIdx.x) >> 5;
    const int lane = threadIdx.x & 31;
    if (warp >= BB * NN) return;
    const int row = warp;
    const int b = row >> 12;
    const int n = row & (NN - 1);
    const float* vn = g_xnt + ((size_t)b * NN + n) * CC;
    const float* sqb = g_sq + (size_t)b * NN;

    unsigned long long key = 0xFFFFFFFFFFFFFFFFULL;
    if (lane < NCAND) {
        int m = g_cand[(size_t)row * NCAND + lane];
        const float* vm = g_xnt + ((size_t)b * NN + m) * CC;
        float acc = 0.f;
        #pragma unroll 4
        for (int c4 = 0; c4 < CC / 4; c4++) {
            float4 a = *(const float4*)&vn[c4 * 4];
            float4 bb = *(const float4*)&vm[c4 * 4];
            acc = fmaf(a.x, bb.x, acc);
            acc = fmaf(a.y, bb.y, acc);
            acc = fmaf(a.z, bb.z, acc);
            acc = fmaf(a.w, bb.w, acc);
        }
        float d = (sqb[n] + (-2.0f * acc)) + sqb[m];
        key = ((unsigned long long)ford(d) << 32) | (unsigned)m;
    }

    const size_t L = (size_t)BB * NN * KK;
    const size_t outbase = (size_t)row * KK;
    for (int k = 0; k < KK; k++) {
        unsigned long long mn = key;
        #pragma unroll
        for (int off = 16; off > 0; off >>= 1) {
            unsigned long long o = __shfl_xor_sync(0xFFFFFFFFu, mn, off);
            mn = (o < mn) ? o : mn;
        }
        if (key == mn) key = 0xFFFFFFFFFFFFFFFFULL;
        if (lane == 0)
            out[outbase + k] = (float)((int)(mn & 0xFFFFFFFFu) + b * NN);
    }
    if (lane < KK) out[L + outbase + lane] = (float)(n + b * NN);
}

// ---------------------------------------------------------------------------
extern "C" void kernel_launch(void* const* d_in, const int* in_sizes, int n_in,
                              void* d_out, int out_size) {
    const float* x = (const float*)d_in[0];
    float* out = (float*)d_out;

    { dim3 grid(8, BB); normalize_kernel<<<grid, 256>>>(x); }
    { dim3 grid(CC / 32, NN / 32, BB); transpose_kernel<<<grid, dim3(32, 8)>>>(); }
    { dim3 grid(272, BB); dist_gemm_h2_kernel<<<grid, 256>>>(); }
    { int rows = BB * NN; select_cand_kernel<<<(rows * 32 + 255) / 256, 256>>>(); }
    { int rows = BB * NN; rescore_kernel<<<(rows * 32 + 255) / 256, 256>>>(out); }
}

// round 17
// speedup vs baseline: 2.5023x; 1.1708x over previous
#include <cuda_runtime.h>
#include <cstdint>

#define BB 4
#define CC 192
#define NN 4096
#define KK 9
#define TK 16

__device__ __align__(256) float g_xn[(size_t)BB * CC * NN];   // normalized pts [b][c][n]
__device__ __align__(256) float g_sq[(size_t)BB * NN];        // per-point sum of squares
__device__ __align__(256) float g_dist[(size_t)BB * NN * NN]; // distance matrix

__device__ __forceinline__ void cp_async16(void* smem_dst, const void* gmem_src) {
    unsigned saddr = (unsigned)__cvta_generic_to_shared(smem_dst);
    asm volatile("cp.async.ca.shared.global [%0], [%1], 16;\n" :: "r"(saddr), "l"(gmem_src));
}
__device__ __forceinline__ void cp_commit() { asm volatile("cp.async.commit_group;\n"); }
template <int N>
__device__ __forceinline__ void cp_wait() { asm volatile("cp.async.wait_group %0;\n" :: "n"(N)); }

// ---------------------------------------------------------------------------
// Kernel 1: L2-normalize over channel dim. x layout [B][C][N], N = H*W.
// ---------------------------------------------------------------------------
__global__ void normalize_kernel(const float* __restrict__ x) {
    int b = blockIdx.y;
    int n = blockIdx.x * blockDim.x + threadIdx.x;
    if (n >= NN) return;
    const float* xb = x + (size_t)b * CC * NN + n;
    float s = 0.f;
    #pragma unroll 16
    for (int c = 0; c < CC; c++) { float v = xb[(size_t)c * NN]; s += v * v; }
    float denom = fmaxf(sqrtf(s), 1e-12f);
    float* xnb = g_xn + (size_t)b * CC * NN + n;
    float sq = 0.f;
    #pragma unroll 16
    for (int c = 0; c < CC; c++) {
        float p = xb[(size_t)c * NN] / denom;
        xnb[(size_t)c * NN] = p;
        sq += p * p;
    }
    g_sq[(size_t)b * NN + n] = sq;
}

// ---------------------------------------------------------------------------
// Kernel 2: symmetric distance GEMM, cp.async double-buffered, INTERLEAVED
// micro-tile mapping (conflict-free fragment LDS):
//   thread (tx,ty) owns rows {ty+16i} and cols {tx+16j}, i,j in 0..7.
// Same c-ascending accumulation order as rounds 8-12 -> identical dist bits.
// ---------------------------------------------------------------------------
__global__ __launch_bounds__(256) void dist_gemm_sym_kernel() {
    __shared__ union {
        float ab[2][2][TK][128];   // [buf][A=0/B=1][k][col]  -> 32 KB
        float ts[128 * 33];        // mirror staging [n][m_local(32)+pad]
    } sm;

    // map linear tile index -> (bi, bj) with bi <= bj
    int u = blockIdx.x;
    int bi = 0, rowlen = 32;
    while (u >= rowlen) { u -= rowlen; rowlen--; bi++; }
    const int bj = bi + u;

    const int b  = blockIdx.z;
    const int n0 = bi * 128;
    const int m0 = bj * 128;
    const float* base = g_xn + (size_t)b * CC * NN;
    const int tid = threadIdx.x;
    const int tx = tid & 15;        // m interleave lane
    const int ty = tid >> 4;        // n interleave lane

    const int lr = tid >> 5;        // loader k-row 0..7
    const int lc = (tid & 31) * 4;  // loader float4 col slot

    const int NT = CC / TK;         // 12

    // preload tile 0 into buffer 0
    {
        const float* s0 = base + (size_t)lr * NN;
        const float* s1 = base + (size_t)(lr + 8) * NN;
        cp_async16(&sm.ab[0][0][lr][lc],     s0 + n0 + lc);
        cp_async16(&sm.ab[0][0][lr + 8][lc], s1 + n0 + lc);
        cp_async16(&sm.ab[0][1][lr][lc],     s0 + m0 + lc);
        cp_async16(&sm.ab[0][1][lr + 8][lc], s1 + m0 + lc);
        cp_commit();
    }

    float acc[8][8];
    #pragma unroll
    for (int i = 0; i < 8; i++)
        #pragma unroll
        for (int j = 0; j < 8; j++) acc[i][j] = 0.f;

    #pragma unroll 1
    for (int t = 0; t < NT; t++) {
        const int cur = t & 1;

        if (t + 1 < NT) {
            const int c1 = (t + 1) * TK;
            const float* s0 = base + (size_t)(c1 + lr) * NN;
            const float* s1 = base + (size_t)(c1 + lr + 8) * NN;
            cp_async16(&sm.ab[cur ^ 1][0][lr][lc],     s0 + n0 + lc);
            cp_async16(&sm.ab[cur ^ 1][0][lr + 8][lc], s1 + n0 + lc);
            cp_async16(&sm.ab[cur ^ 1][1][lr][lc],     s0 + m0 + lc);
            cp_async16(&sm.ab[cur ^ 1][1][lr + 8][lc], s1 + m0 + lc);
            cp_commit();
            cp_wait<1>();
        } else {
            cp_wait<0>();
        }
        __syncthreads();

        const float (*As)[128] = sm.ab[cur][0];
        const float (*Bs)[128] = sm.ab[cur][1];
        #pragma unroll
        for (int kk = 0; kk < TK; kk++) {
            float a[8], bv[8];
            #pragma unroll
            for (int i = 0; i < 8; i++) a[i]  = As[kk][ty + 16 * i];   // broadcast
            #pragma unroll
            for (int j = 0; j < 8; j++) bv[j] = Bs[kk][tx + 16 * j];   // conflict-free
            #pragma unroll
            for (int i = 0; i < 8; i++)
                #pragma unroll
                for (int j = 0; j < 8; j++)
                    acc[i][j] += a[i] * bv[j];
        }
        __syncthreads();
    }

    const float* sqb = g_sq + (size_t)b * NN;

    // ---- normal tile: dist[n0+ty+16i][m0+tx+16j] ----
    {
        float sqm[8];
        #pragma unroll
        for (int j = 0; j < 8; j++) sqm[j] = sqb[m0 + tx + 16 * j];
        #pragma unroll
        for (int i = 0; i < 8; i++) {
            int n = n0 + ty + 16 * i;
            float sqn = sqb[n];
            float* drow = g_dist + ((size_t)b * NN + n) * NN + m0 + tx;
            #pragma unroll
            for (int j = 0; j < 8; j++)
                drow[16 * j] = (sqn + (-2.0f * acc[i][j])) + sqm[j];
        }
    }

    // ---- mirrored tile: dist[m][n] = (sq_m + (-2*dot)) + sq_n ----
    if (bi != bj) {
        #pragma unroll 1
        for (int c = 0; c < 4; c++) {            // m'-chunks of 32: j in {2c,2c+1}
            __syncthreads();
            #pragma unroll
            for (int i = 0; i < 8; i++) {
                #pragma unroll
                for (int jl = 0; jl < 2; jl++) {
                    int j = 2 * c + jl;
                    sm.ts[(size_t)(ty + 16 * i) * 33 + (tx + 16 * jl)] = acc[i][j];
                }
            }
            __syncthreads();
            const int rl = tid >> 3;             // m_local 0..31
            const int cg = (tid & 7) * 16;       // n col group base
            int m = m0 + c * 32 + rl;
            float sqm_v = sqb[m];
            float* drow = g_dist + ((size_t)b * NN + m) * NN + n0;
            float o[16];
            #pragma unroll
            for (int cc = 0; cc < 16; cc++) {
                float dot = sm.ts[(size_t)(cg + cc) * 33 + rl];
                o[cc] = (sqm_v + (-2.0f * dot)) + sqb[n0 + cg + cc];
            }
            #pragma unroll
            for (int q = 0; q < 4; q++)
                *(float4*)&drow[cg + q * 4] =
                    make_float4(o[q*4], o[q*4+1], o[q*4+2], o[q*4+3]);
        }
    }
}

// ---------------------------------------------------------------------------
// Kernel 3: warp-per-row top-10 ascending (dist, idx); drop rank 0 (self).
// ---------------------------------------------------------------------------
__device__ __forceinline__ unsigned ford(float f) {
    unsigned u = __float_as_uint(f);
    return (u & 0x80000000u) ? ~u : (u | 0x80000000u);
}

__global__ void select_topk_kernel(float* __restrict__ out) {
    const int warp = (blockIdx.x * blockDim.x + threadIdx.x) >> 5;
    const int lane = threadIdx.x & 31;
    if (warp >= BB * NN) return;
    const int row = warp;
    const int b = row >> 12;
    const int n = row & (NN - 1);
    const float* drow = g_dist + (size_t)row * NN;

    float v[10]; int id[10];
    #pragma unroll
    for (int k = 0; k < 10; k++) { v[k] = 3.4e38f; id[k] = 0x7FFFFFFF; }

    for (int m = lane; m < NN; m += 32) {
        float val = drow[m];
        if ((val < v[9]) || (val == v[9] && m < id[9])) {
            v[9] = val; id[9] = m;
            #pragma unroll
            for (int k = 9; k > 0; k--) {
                bool sw = (v[k] < v[k-1]) || (v[k] == v[k-1] && id[k] < id[k-1]);
                if (sw) {
                    float tv = v[k]; v[k] = v[k-1]; v[k-1] = tv;
                    int ti = id[k]; id[k] = id[k-1]; id[k-1] = ti;
                }
            }
        }
    }

    const size_t L = (size_t)BB * NN * KK;
    const size_t outbase = (size_t)row * KK;
    int pos = 0;
    for (int k = 0; k < 10; k++) {
        unsigned long long myk = (pos < 10)
            ? (((unsigned long long)ford(v[pos]) << 32) | (unsigned)id[pos])
            : 0xFFFFFFFFFFFFFFFFULL;
        unsigned long long mn = myk;
        #pragma unroll
        for (int off = 16; off > 0; off >>= 1) {
            unsigned long long o = __shfl_xor_sync(0xFFFFFFFFu, mn, off);
            mn = (o < mn) ? o : mn;
        }
        if (myk == mn) pos++;
        if (k > 0 && lane == 0)
            out[outbase + (k - 1)] = (float)((int)(mn & 0xFFFFFFFFu) + b * NN);
    }
    if (lane < KK) out[L + outbase + lane] = (float)(n + b * NN);
}

// ---------------------------------------------------------------------------
extern "C" void kernel_launch(void* const* d_in, const int* in_sizes, int n_in,
                              void* d_out, int out_size) {
    const float* x = (const float*)d_in[0];
    float* out = (float*)d_out;

    { dim3 grid(NN / 256, BB); normalize_kernel<<<grid, 256>>>(x); }
    { dim3 grid(528, 1, BB); dist_gemm_sym_kernel<<<grid, 256>>>(); }
    { int rows = BB * NN; select_topk_kernel<<<(rows * 32 + 255) / 256, 256>>>(out); }
}